// round 3
// baseline (speedup 1.0000x reference)
#include <cuda_runtime.h>
#include <cuda_bf16.h>
#include <math.h>

#define N_TOK 1024
#define HDIM  2048
#define IDIM  1408
#define NEXP  8
#define TOPK  2
#define ISH   2816
#define NSLOT (N_TOK * TOPK)   // 2048

#define BM 128
#define BN 128
#define BK 16
#define PAD 4                   // smem row stride 132 floats

// ---------------- scratch (static device memory; no allocations) ----------------
__device__ int   d_cnt[NEXP];
__device__ int   d_cnt2[NEXP];
__device__ int   d_off[NEXP];
__device__ int   d_sel[N_TOK * TOPK];
__device__ float d_selw[N_TOK * TOPK];
__device__ int   d_tok[NSLOT];
__device__ float d_wt[NSLOT];
// buf1: shared-gate activations, then routed-gate activations (reused sequentially)
// buf2: shared-up activations, then routed-up activations
__device__ float d_buf1[(size_t)NSLOT * IDIM];   // 2048*1408 == 1024*2816
__device__ float d_buf2[(size_t)NSLOT * IDIM];

// ---------------- helpers: packed f32x2 FMA (Blackwell) ----------------
__device__ __forceinline__ unsigned long long pack2f(float v) {
    unsigned long long r;
    unsigned int u = __float_as_uint(v);
    asm("mov.b64 %0, {%1, %1};" : "=l"(r) : "r"(u));
    return r;
}
__device__ __forceinline__ void ffma2(unsigned long long& c,
                                      unsigned long long a,
                                      unsigned long long b) {
    asm("fma.rn.f32x2 %0, %1, %2, %0;" : "+l"(c) : "l"(a), "l"(b));
}

// ---------------- small kernels ----------------
__global__ void zero_kernel() {
    int t = threadIdx.x;
    if (t < NEXP) { d_cnt[t] = 0; d_cnt2[t] = 0; }
}

// 1 block per token; 8 warps = 8 experts
__global__ void router_kernel(const float* __restrict__ x,
                              const float* __restrict__ gw) {
    int n    = blockIdx.x;
    int wid  = threadIdx.x >> 5;
    int lane = threadIdx.x & 31;
    __shared__ float logits[NEXP];
    const float* xr = x  + (size_t)n   * HDIM;
    const float* gr = gw + (size_t)wid * HDIM;
    float s = 0.f;
    for (int h = lane; h < HDIM; h += 32) s = fmaf(xr[h], gr[h], s);
    #pragma unroll
    for (int o = 16; o > 0; o >>= 1) s += __shfl_xor_sync(0xffffffffu, s, o);
    if (lane == 0) logits[wid] = s;
    __syncthreads();
    if (threadIdx.x == 0) {
        float mx = logits[0];
        #pragma unroll
        for (int e = 1; e < NEXP; ++e) mx = fmaxf(mx, logits[e]);
        float p[NEXP]; float sum = 0.f;
        #pragma unroll
        for (int e = 0; e < NEXP; ++e) { p[e] = expf(logits[e] - mx); sum += p[e]; }
        float inv = 1.f / sum;
        #pragma unroll
        for (int e = 0; e < NEXP; ++e) p[e] *= inv;
        // top-2 (first occurrence wins on ties, matching lax.top_k)
        float p1 = p[0]; int i1 = 0;
        float p2 = -1.f; int i2 = -1;
        #pragma unroll
        for (int e = 1; e < NEXP; ++e) {
            if (p[e] > p1)      { p2 = p1; i2 = i1; p1 = p[e]; i1 = e; }
            else if (p[e] > p2) { p2 = p[e]; i2 = e; }
        }
        float ws = p1 + p2 + 1e-20f;
        float w1 = p1 / ws, w2 = p2 / ws;
        d_sel[n * 2]      = i1; d_selw[n * 2]     = w1;
        d_sel[n * 2 + 1]  = i2; d_selw[n * 2 + 1] = w2;
        atomicAdd(&d_cnt[i1], 1);
        atomicAdd(&d_cnt[i2], 1);
    }
}

__global__ void offsets_kernel() {
    if (threadIdx.x == 0) {
        int acc = 0;
        #pragma unroll
        for (int e = 0; e < NEXP; ++e) { d_off[e] = acc; acc += d_cnt[e]; }
    }
}

__global__ void scatter_kernel() {
    int n = blockIdx.x * blockDim.x + threadIdx.x;
    if (n >= N_TOK) return;
    #pragma unroll
    for (int k = 0; k < TOPK; ++k) {
        int   e = d_sel[n * 2 + k];
        float w = d_selw[n * 2 + k];
        int pos  = atomicAdd(&d_cnt2[e], 1);
        int slot = d_off[e] + pos;
        d_tok[slot] = n;
        d_wt[slot]  = w;
    }
}

__global__ void silu_mul_kernel(const float* __restrict__ g,
                                const float* __restrict__ u,
                                float* __restrict__ o, int n) {
    int i = blockIdx.x * blockDim.x + threadIdx.x;
    if (i >= n) return;
    float gv = g[i];
    float s  = gv / (1.f + expf(-gv));
    o[i] = s * u[i];
}

// ---------------- the NT-SGEMM: C[m,n] = sum_k A[m,k] * B[n,k] ----------------
// MODE 0: plain A (row m), plain store C[m*N+n]
// MODE 1: routed GEMM1: per-expert (blockIdx.z), A rows gathered via d_tok,
//         store C[(off+m)*N+n]
// MODE 2: routed GEMM2: per-expert, A rows = slots (off+m), epilogue:
//         atomicAdd(out[tok*N+n], wt * acc)
template <int MODE>
__global__ __launch_bounds__(256, 2)
void gemm_nt(const float* __restrict__ A, const float* __restrict__ B,
             float* __restrict__ C, int M, int N, int K) {
    int e = blockIdx.z;
    int base = 0;
    if (MODE >= 1) {
        M    = d_cnt[e];
        base = d_off[e];
        B   += (size_t)e * N * K;
    }
    int m0 = blockIdx.y * BM;
    if (m0 >= M) return;
    int n0 = blockIdx.x * BN;

    __shared__ __align__(16) float As[BK][BM + PAD];
    __shared__ __align__(16) float Bs[BK][BN + PAD];

    int t     = threadIdx.x;
    int lrow  = t >> 2;          // 0..63
    int lk4   = (t & 3) * 4;     // 0,4,8,12
    int tx4   = (t & 15) * 4;
    int ty4   = (t >> 4) * 4;

    const float* aptr[2];
    bool avalid[2];
    #pragma unroll
    for (int it = 0; it < 2; ++it) {
        int m = m0 + lrow + it * 64;
        bool v = (m < M);
        int row;
        if (MODE == 1)      row = v ? d_tok[base + m] : 0;
        else if (MODE == 2) row = v ? (base + m) : 0;
        else                row = v ? m : 0;
        aptr[it]   = A + (size_t)row * K;
        avalid[it] = v;
    }
    const float* bptr[2];
    #pragma unroll
    for (int it = 0; it < 2; ++it)
        bptr[it] = B + (size_t)(n0 + lrow + it * 64) * K;

    unsigned long long acc[8][4];
    #pragma unroll
    for (int i = 0; i < 8; ++i)
        #pragma unroll
        for (int j = 0; j < 4; ++j) acc[i][j] = 0ull;

    const float4 z4 = make_float4(0.f, 0.f, 0.f, 0.f);
    float4 ra[2], rb[2];

    // prologue: tile 0
    #pragma unroll
    for (int it = 0; it < 2; ++it) {
        ra[it] = avalid[it] ? *(const float4*)(aptr[it] + lk4) : z4;
        rb[it] = *(const float4*)(bptr[it] + lk4);
    }
    #pragma unroll
    for (int it = 0; it < 2; ++it) {
        int r = lrow + it * 64;
        As[lk4 + 0][r] = ra[it].x; As[lk4 + 1][r] = ra[it].y;
        As[lk4 + 2][r] = ra[it].z; As[lk4 + 3][r] = ra[it].w;
        Bs[lk4 + 0][r] = rb[it].x; Bs[lk4 + 1][r] = rb[it].y;
        Bs[lk4 + 2][r] = rb[it].z; Bs[lk4 + 3][r] = rb[it].w;
    }
    __syncthreads();

    int KT = K / BK;
    for (int kt = 1; kt <= KT; ++kt) {
        bool has_next = (kt < KT);
        if (has_next) {
            int ko = kt * BK + lk4;
            #pragma unroll
            for (int it = 0; it < 2; ++it) {
                ra[it] = avalid[it] ? *(const float4*)(aptr[it] + ko) : z4;
                rb[it] = *(const float4*)(bptr[it] + ko);
            }
        }
        #pragma unroll
        for (int k = 0; k < BK; ++k) {
            float4 a0 = *(const float4*)&As[k][ty4];
            float4 a1 = *(const float4*)&As[k][64 + ty4];
            const unsigned long long* bp0 =
                reinterpret_cast<const unsigned long long*>(&Bs[k][tx4]);
            const unsigned long long* bp1 =
                reinterpret_cast<const unsigned long long*>(&Bs[k][64 + tx4]);
            unsigned long long pb0 = bp0[0], pb1 = bp0[1];
            unsigned long long pb2 = bp1[0], pb3 = bp1[1];
            float av[8] = {a0.x, a0.y, a0.z, a0.w, a1.x, a1.y, a1.z, a1.w};
            #pragma unroll
            for (int i = 0; i < 8; ++i) {
                unsigned long long pa = pack2f(av[i]);
                ffma2(acc[i][0], pa, pb0);
                ffma2(acc[i][1], pa, pb1);
                ffma2(acc[i][2], pa, pb2);
                ffma2(acc[i][3], pa, pb3);
            }
        }
        __syncthreads();
        if (has_next) {
            #pragma unroll
            for (int it = 0; it < 2; ++it) {
                int r = lrow + it * 64;
                As[lk4 + 0][r] = ra[it].x; As[lk4 + 1][r] = ra[it].y;
                As[lk4 + 2][r] = ra[it].z; As[lk4 + 3][r] = ra[it].w;
                Bs[lk4 + 0][r] = rb[it].x; Bs[lk4 + 1][r] = rb[it].y;
                Bs[lk4 + 2][r] = rb[it].z; Bs[lk4 + 3][r] = rb[it].w;
            }
            __syncthreads();
        }
    }

    // epilogue
    #pragma unroll
    for (int i = 0; i < 8; ++i) {
        int m = m0 + ((i < 4) ? (ty4 + i) : (64 + ty4 + i - 4));
        if (m >= M) continue;
        float v[8];
        #pragma unroll
        for (int j = 0; j < 4; ++j) {
            v[2 * j]     = __uint_as_float((unsigned int)(acc[i][j]));
            v[2 * j + 1] = __uint_as_float((unsigned int)(acc[i][j] >> 32));
        }
        if (MODE == 2) {
            int   s   = base + m;
            int   tok = d_tok[s];
            float w   = d_wt[s];
            float* orow = C + (size_t)tok * N;
            #pragma unroll
            for (int j = 0; j < 4; ++j)
                atomicAdd(&orow[n0 + tx4 + j], w * v[j]);
            #pragma unroll
            for (int j = 0; j < 4; ++j)
                atomicAdd(&orow[n0 + 64 + tx4 + j], w * v[4 + j]);
        } else {
            size_t crow = (MODE == 1) ? (size_t)(base + m) : (size_t)m;
            float* cp = C + crow * N;
            float4 s0 = make_float4(v[0], v[1], v[2], v[3]);
            float4 s1 = make_float4(v[4], v[5], v[6], v[7]);
            *(float4*)&cp[n0 + tx4]      = s0;
            *(float4*)&cp[n0 + 64 + tx4] = s1;
        }
    }
}

// ---------------- launch ----------------
extern "C" void kernel_launch(void* const* d_in, const int* in_sizes, int n_in,
                              void* d_out, int out_size) {
    const float* x   = (const float*)d_in[0];
    const float* gw  = (const float*)d_in[1];
    const float* eg  = (const float*)d_in[2];
    const float* eu  = (const float*)d_in[3];
    const float* ed  = (const float*)d_in[4];
    const float* sg  = (const float*)d_in[5];
    const float* su  = (const float*)d_in[6];
    const float* sd  = (const float*)d_in[7];
    float* out = (float*)d_out;

    float* buf1; float* buf2;
    cudaGetSymbolAddress((void**)&buf1, d_buf1);
    cudaGetSymbolAddress((void**)&buf2, d_buf2);

    // routing
    zero_kernel<<<1, 32>>>();
    router_kernel<<<N_TOK, 256>>>(x, gw);
    offsets_kernel<<<1, 32>>>();
    scatter_kernel<<<4, 256>>>();

    // shared expert (writes every element of out -> initializes it)
    gemm_nt<0><<<dim3(ISH / BN, N_TOK / BM, 1), 256>>>(x, sg, buf1, N_TOK, ISH, HDIM);
    gemm_nt<0><<<dim3(ISH / BN, N_TOK / BM, 1), 256>>>(x, su, buf2, N_TOK, ISH, HDIM);
    {
        int n = N_TOK * ISH;
        silu_mul_kernel<<<(n + 255) / 256, 256>>>(buf1, buf2, buf1, n);
    }
    gemm_nt<0><<<dim3(HDIM / BN, N_TOK / BM, 1), 256>>>(buf1, sd, out, N_TOK, HDIM, ISH);

    // routed experts (sparse: exactly 2048 token-expert slots)
    gemm_nt<1><<<dim3(IDIM / BN, N_TOK / BM, NEXP), 256>>>(x, eg, buf1, 0, IDIM, HDIM);
    gemm_nt<1><<<dim3(IDIM / BN, N_TOK / BM, NEXP), 256>>>(x, eu, buf2, 0, IDIM, HDIM);
    {
        int n = NSLOT * IDIM;
        silu_mul_kernel<<<(n + 255) / 256, 256>>>(buf1, buf2, buf1, n);
    }
    gemm_nt<2><<<dim3(HDIM / BN, N_TOK / BM, NEXP), 256>>>(buf1, ed, out, 0, HDIM, IDIM);
}

// round 5
// speedup vs baseline: 1.9877x; 1.9877x over previous
#include <cuda_runtime.h>
#include <cuda_bf16.h>
#include <math.h>
#include <stdint.h>

#define N_TOK 1024
#define HDIM  2048
#define IDIM  1408
#define NEXP  8
#define ISH   2816
#define NSLOT 2048
#define ACT_ELEMS (2048 * 1408)   // == 1024*2816

#define BK  32                     // k per chunk (elements)
#define LDS 40                     // smem row stride in bf16 (padded)
#define TILE_BYTES (128 * LDS * 2) // 10240

// ---------------- scratch (static device memory) ----------------
__device__ int   d_cnt[NEXP];
__device__ int   d_cnt2[NEXP];
__device__ int   d_off[NEXP];
__device__ int   d_sel[N_TOK * 2];
__device__ float d_selw[N_TOK * 2];
__device__ int   d_tok[NSLOT];
__device__ float d_wt[NSLOT];
__device__ __align__(16) __nv_bfloat16 d_actHi[ACT_ELEMS];
__device__ __align__(16) __nv_bfloat16 d_actLo[ACT_ELEMS];

// ---------------- helpers ----------------
__device__ __forceinline__ uint32_t smem_u32(const void* p) {
    return (uint32_t)__cvta_generic_to_shared(p);
}
__device__ __forceinline__ void sts128(uint32_t addr, uint4 v) {
    asm volatile("st.shared.v4.b32 [%0], {%1, %2, %3, %4};"
                 :: "r"(addr), "r"(v.x), "r"(v.y), "r"(v.z), "r"(v.w));
}
__device__ __forceinline__ void ldsm_x4(uint32_t& r0, uint32_t& r1,
                                        uint32_t& r2, uint32_t& r3, uint32_t a) {
    asm volatile("ldmatrix.sync.aligned.m8n8.x4.shared.b16 {%0,%1,%2,%3}, [%4];"
                 : "=r"(r0), "=r"(r1), "=r"(r2), "=r"(r3) : "r"(a));
}
__device__ __forceinline__ void ldsm_x2(uint32_t& r0, uint32_t& r1, uint32_t a) {
    asm volatile("ldmatrix.sync.aligned.m8n8.x2.shared.b16 {%0,%1}, [%2];"
                 : "=r"(r0), "=r"(r1) : "r"(a));
}
__device__ __forceinline__ void mma_bf16(float* c, const uint32_t* a,
                                         const uint32_t* b) {
    asm volatile(
        "mma.sync.aligned.m16n8k16.row.col.f32.bf16.bf16.f32 "
        "{%0,%1,%2,%3}, {%4,%5,%6,%7}, {%8,%9}, {%0,%1,%2,%3};"
        : "+f"(c[0]), "+f"(c[1]), "+f"(c[2]), "+f"(c[3])
        : "r"(a[0]), "r"(a[1]), "r"(a[2]), "r"(a[3]), "r"(b[0]), "r"(b[1]));
}
__device__ __forceinline__ uint32_t bf2u(__nv_bfloat162 v) {
    return *reinterpret_cast<uint32_t*>(&v);
}
// split 8 floats -> bf16 hi pack + bf16 lo pack
__device__ __forceinline__ void cvt8(float4 q0, float4 q1, uint4& hi, uint4& lo) {
    __nv_bfloat162 h0 = __floats2bfloat162_rn(q0.x, q0.y);
    __nv_bfloat162 h1 = __floats2bfloat162_rn(q0.z, q0.w);
    __nv_bfloat162 h2 = __floats2bfloat162_rn(q1.x, q1.y);
    __nv_bfloat162 h3 = __floats2bfloat162_rn(q1.z, q1.w);
    __nv_bfloat162 l0 = __floats2bfloat162_rn(q0.x - __bfloat162float(h0.x),
                                              q0.y - __bfloat162float(h0.y));
    __nv_bfloat162 l1 = __floats2bfloat162_rn(q0.z - __bfloat162float(h1.x),
                                              q0.w - __bfloat162float(h1.y));
    __nv_bfloat162 l2 = __floats2bfloat162_rn(q1.x - __bfloat162float(h2.x),
                                              q1.y - __bfloat162float(h2.y));
    __nv_bfloat162 l3 = __floats2bfloat162_rn(q1.z - __bfloat162float(h3.x),
                                              q1.w - __bfloat162float(h3.y));
    hi = make_uint4(bf2u(h0), bf2u(h1), bf2u(h2), bf2u(h3));
    lo = make_uint4(bf2u(l0), bf2u(l1), bf2u(l2), bf2u(l3));
}

// ---------------- small kernels ----------------
__global__ void zero_kernel() {
    int t = threadIdx.x;
    if (t < NEXP) { d_cnt[t] = 0; d_cnt2[t] = 0; }
}

__global__ void router_kernel(const float* __restrict__ x,
                              const float* __restrict__ gw) {
    int n    = blockIdx.x;
    int wid  = threadIdx.x >> 5;
    int lane = threadIdx.x & 31;
    __shared__ float logits[NEXP];
    const float* xr = x  + (size_t)n   * HDIM;
    const float* gr = gw + (size_t)wid * HDIM;
    float s = 0.f;
    for (int h = lane; h < HDIM; h += 32) s = fmaf(xr[h], gr[h], s);
    #pragma unroll
    for (int o = 16; o > 0; o >>= 1) s += __shfl_xor_sync(0xffffffffu, s, o);
    if (lane == 0) logits[wid] = s;
    __syncthreads();
    if (threadIdx.x == 0) {
        float mx = logits[0];
        #pragma unroll
        for (int e = 1; e < NEXP; ++e) mx = fmaxf(mx, logits[e]);
        float p[NEXP]; float sum = 0.f;
        #pragma unroll
        for (int e = 0; e < NEXP; ++e) { p[e] = expf(logits[e] - mx); sum += p[e]; }
        float inv = 1.f / sum;
        #pragma unroll
        for (int e = 0; e < NEXP; ++e) p[e] *= inv;
        float p1 = p[0]; int i1 = 0;
        float p2 = -1.f; int i2 = -1;
        #pragma unroll
        for (int e = 1; e < NEXP; ++e) {
            if (p[e] > p1)      { p2 = p1; i2 = i1; p1 = p[e]; i1 = e; }
            else if (p[e] > p2) { p2 = p[e]; i2 = e; }
        }
        float ws = p1 + p2 + 1e-20f;
        d_sel[n * 2]     = i1; d_selw[n * 2]     = p1 / ws;
        d_sel[n * 2 + 1] = i2; d_selw[n * 2 + 1] = p2 / ws;
        atomicAdd(&d_cnt[i1], 1);
        atomicAdd(&d_cnt[i2], 1);
    }
}

__global__ void offsets_kernel() {
    if (threadIdx.x == 0) {
        int acc = 0;
        #pragma unroll
        for (int e = 0; e < NEXP; ++e) { d_off[e] = acc; acc += d_cnt[e]; }
    }
}

__global__ void scatter_kernel() {
    int n = blockIdx.x * blockDim.x + threadIdx.x;
    if (n >= N_TOK) return;
    #pragma unroll
    for (int k = 0; k < 2; ++k) {
        int   e = d_sel[n * 2 + k];
        float w = d_selw[n * 2 + k];
        int pos  = atomicAdd(&d_cnt2[e], 1);
        int slot = d_off[e] + pos;
        d_tok[slot] = n;
        d_wt[slot]  = w;
    }
}

// ================= GEMM 1: fused gate+up, silu*mul epilogue ====================
// 512 threads, 16 warps. Warps 0-7: gate tile; warps 8-15: up tile.
// C[m,n] = sum_k A[m,k] * B[n,k] via bf16 hi/lo 3-term mma.sync.
template <bool ROUTED>
__global__ __launch_bounds__(512, 1)
void gemm_gu(const float* __restrict__ X,
             const float* __restrict__ Bg,
             const float* __restrict__ Bu,
             __nv_bfloat16* __restrict__ actHi,
             __nv_bfloat16* __restrict__ actLo,
             int M, int N, int K)
{
    int e = blockIdx.z, base = 0;
    if (ROUTED) {
        M = d_cnt[e]; base = d_off[e];
        Bg += (size_t)e * N * K;
        Bu += (size_t)e * N * K;
    }
    int m0 = blockIdx.y * 128;
    if (m0 >= M) return;
    int n0 = blockIdx.x * 128;

    extern __shared__ char smem[];
    uint32_t sb  = smem_u32(smem);
    uint32_t sAh = sb,                  sAl = sb + TILE_BYTES;
    uint32_t sGh = sb + 2 * TILE_BYTES, sGl = sb + 3 * TILE_BYTES;
    uint32_t sUh = sb + 4 * TILE_BYTES, sUl = sb + 5 * TILE_BYTES;
    float* cuS = (float*)smem;          // overlapped exchange region (post-loop)

    int t = threadIdx.x, lane = t & 31, wid = t >> 5;
    int lrow = t >> 2, lcol = (t & 3) * 8;

    bool aval = (m0 + lrow) < M;
    int  arow = ROUTED ? (aval ? d_tok[base + m0 + lrow] : 0)
                       : (aval ? m0 + lrow : 0);
    const float* aP = X  + (size_t)arow * K + lcol;
    const float* gP = Bg + (size_t)(n0 + lrow) * K + lcol;
    const float* uP = Bu + (size_t)(n0 + lrow) * K + lcol;
    uint32_t stO = (uint32_t)(lrow * LDS + lcol) * 2u;

    int  gw   = wid & 7;
    int  wm   = (gw & 1) * 64, wn = (gw >> 1) * 32;
    bool isUp = wid >= 8;
    uint32_t sBh = isUp ? sUh : sGh;
    uint32_t sBl = isUp ? sUl : sGl;

    float acc[4][4][4];
    #pragma unroll
    for (int i = 0; i < 4; ++i)
        #pragma unroll
        for (int j = 0; j < 4; ++j)
            #pragma unroll
            for (int q = 0; q < 4; ++q) acc[i][j][q] = 0.f;

    int KT = K / BK;
    for (int ch = 0; ch < KT; ++ch) {
        int k0 = ch * BK;
        {
            float4 q0, q1; uint4 hi, lo;
            if (aval) { q0 = *(const float4*)(aP + k0); q1 = *(const float4*)(aP + k0 + 4); }
            else      { q0 = make_float4(0, 0, 0, 0); q1 = q0; }
            cvt8(q0, q1, hi, lo);
            sts128(sAh + stO, hi); sts128(sAl + stO, lo);
            q0 = *(const float4*)(gP + k0); q1 = *(const float4*)(gP + k0 + 4);
            cvt8(q0, q1, hi, lo);
            sts128(sGh + stO, hi); sts128(sGl + stO, lo);
            q0 = *(const float4*)(uP + k0); q1 = *(const float4*)(uP + k0 + 4);
            cvt8(q0, q1, hi, lo);
            sts128(sUh + stO, hi); sts128(sUl + stO, lo);
        }
        __syncthreads();
        #pragma unroll
        for (int s = 0; s < 2; ++s) {
            uint32_t bh[4][2], bl[4][2];
            uint32_t bOff = (uint32_t)(((wn + (lane & 7)) * LDS
                           + s * 16 + ((lane >> 3) & 1) * 8) * 2);
            #pragma unroll
            for (int j = 0; j < 4; ++j) {
                ldsm_x2(bh[j][0], bh[j][1], sBh + bOff + j * (8 * LDS * 2));
                ldsm_x2(bl[j][0], bl[j][1], sBl + bOff + j * (8 * LDS * 2));
            }
            uint32_t aOff = (uint32_t)(((wm + (lane & 15)) * LDS
                           + s * 16 + (lane >> 4) * 8) * 2);
            #pragma unroll
            for (int i = 0; i < 4; ++i) {
                uint32_t ah[4], al[4];
                ldsm_x4(ah[0], ah[1], ah[2], ah[3], sAh + aOff + i * (16 * LDS * 2));
                ldsm_x4(al[0], al[1], al[2], al[3], sAl + aOff + i * (16 * LDS * 2));
                #pragma unroll
                for (int j = 0; j < 4; ++j) {
                    mma_bf16(acc[i][j], ah, bh[j]);
                    mma_bf16(acc[i][j], al, bh[j]);
                    mma_bf16(acc[i][j], ah, bl[j]);
                }
            }
        }
        __syncthreads();
    }

    // exchange: up warps -> smem, gate warps combine + store
    if (isUp) {
        #pragma unroll
        for (int i = 0; i < 4; ++i)
            #pragma unroll
            for (int j = 0; j < 4; ++j) {
                int r = wm + i * 16 + (lane >> 2);
                int c = wn + j * 8 + (lane & 3) * 2;
                *(float2*)&cuS[r * 132 + c]       = make_float2(acc[i][j][0], acc[i][j][1]);
                *(float2*)&cuS[(r + 8) * 132 + c] = make_float2(acc[i][j][2], acc[i][j][3]);
            }
    }
    __syncthreads();
    if (!isUp) {
        #pragma unroll
        for (int i = 0; i < 4; ++i)
            #pragma unroll
            for (int j = 0; j < 4; ++j) {
                int r = wm + i * 16 + (lane >> 2);
                int c = wn + j * 8 + (lane & 3) * 2;
                #pragma unroll
                for (int hh = 0; hh < 2; ++hh) {
                    int rr = r + hh * 8;
                    int mg = m0 + rr;
                    if (mg >= M) continue;
                    float2 uv = *(float2*)&cuS[rr * 132 + c];
                    float g0 = acc[i][j][hh * 2], g1 = acc[i][j][hh * 2 + 1];
                    float a0 = g0 / (1.f + expf(-g0)) * uv.x;
                    float a1 = g1 / (1.f + expf(-g1)) * uv.y;
                    __nv_bfloat162 h = __floats2bfloat162_rn(a0, a1);
                    __nv_bfloat162 l = __floats2bfloat162_rn(
                        a0 - __bfloat162float(h.x), a1 - __bfloat162float(h.y));
                    size_t orow = (size_t)(ROUTED ? base + mg : mg);
                    *(__nv_bfloat162*)(actHi + orow * N + n0 + c) = h;
                    *(__nv_bfloat162*)(actLo + orow * N + n0 + c) = l;
                }
            }
    }
}

// ================= GEMM 2: down projection (N = HDIM) =========================
// A pre-split bf16 (actHi/actLo); W f32 split in-kernel.
// shared: plain store.  routed: atomicAdd(out[tok], w * acc).
template <bool ROUTED>
__global__ __launch_bounds__(512, 1)
void gemm_down(const __nv_bfloat16* __restrict__ AHi,
               const __nv_bfloat16* __restrict__ ALo,
               const float* __restrict__ W,
               float* __restrict__ Out,
               int M, int K)
{
    int e = blockIdx.z, base = 0;
    if (ROUTED) {
        M = d_cnt[e]; base = d_off[e];
        W += (size_t)e * HDIM * K;
    }
    int m0 = blockIdx.y * 128;
    if (m0 >= M) return;
    int n0 = blockIdx.x * 128;

    extern __shared__ char smem[];
    uint32_t sb  = smem_u32(smem);
    uint32_t sAh = sb,                  sAl = sb + TILE_BYTES;
    uint32_t sBh = sb + 2 * TILE_BYTES, sBl = sb + 3 * TILE_BYTES;

    int t = threadIdx.x, lane = t & 31, wid = t >> 5;
    int lrow = t >> 2, lcol = (t & 3) * 8;

    bool aval = (m0 + lrow) < M;
    size_t arow = (size_t)(base + (aval ? m0 + lrow : 0));
    const __nv_bfloat16* ahP = AHi + arow * (size_t)K + lcol;
    const __nv_bfloat16* alP = ALo + arow * (size_t)K + lcol;
    const float* bP = W + (size_t)(n0 + lrow) * K + lcol;
    uint32_t stO = (uint32_t)(lrow * LDS + lcol) * 2u;

    int wm = (wid & 3) * 32, wn = (wid >> 2) * 32;

    float acc[2][4][4];
    #pragma unroll
    for (int i = 0; i < 2; ++i)
        #pragma unroll
        for (int j = 0; j < 4; ++j)
            #pragma unroll
            for (int q = 0; q < 4; ++q) acc[i][j][q] = 0.f;

    uint4 z4 = make_uint4(0, 0, 0, 0);
    int KT = K / BK;
    for (int ch = 0; ch < KT; ++ch) {
        int k0 = ch * BK;
        {
            sts128(sAh + stO, aval ? *(const uint4*)(ahP + k0) : z4);
            sts128(sAl + stO, aval ? *(const uint4*)(alP + k0) : z4);
            float4 q0 = *(const float4*)(bP + k0);
            float4 q1 = *(const float4*)(bP + k0 + 4);
            uint4 hi, lo; cvt8(q0, q1, hi, lo);
            sts128(sBh + stO, hi); sts128(sBl + stO, lo);
        }
        __syncthreads();
        #pragma unroll
        for (int s = 0; s < 2; ++s) {
            uint32_t bh[4][2], bl[4][2];
            uint32_t bOff = (uint32_t)(((wn + (lane & 7)) * LDS
                           + s * 16 + ((lane >> 3) & 1) * 8) * 2);
            #pragma unroll
            for (int j = 0; j < 4; ++j) {
                ldsm_x2(bh[j][0], bh[j][1], sBh + bOff + j * (8 * LDS * 2));
                ldsm_x2(bl[j][0], bl[j][1], sBl + bOff + j * (8 * LDS * 2));
            }
            uint32_t aOff = (uint32_t)(((wm + (lane & 15)) * LDS
                           + s * 16 + (lane >> 4) * 8) * 2);
            #pragma unroll
            for (int i = 0; i < 2; ++i) {
                uint32_t ah[4], al[4];
                ldsm_x4(ah[0], ah[1], ah[2], ah[3], sAh + aOff + i * (16 * LDS * 2));
                ldsm_x4(al[0], al[1], al[2], al[3], sAl + aOff + i * (16 * LDS * 2));
                #pragma unroll
                for (int j = 0; j < 4; ++j) {
                    mma_bf16(acc[i][j], ah, bh[j]);
                    mma_bf16(acc[i][j], al, bh[j]);
                    mma_bf16(acc[i][j], ah, bl[j]);
                }
            }
        }
        __syncthreads();
    }

    #pragma unroll
    for (int i = 0; i < 2; ++i)
        #pragma unroll
        for (int j = 0; j < 4; ++j) {
            int r = wm + i * 16 + (lane >> 2);
            int c = wn + j * 8 + (lane & 3) * 2;
            #pragma unroll
            for (int hh = 0; hh < 2; ++hh) {
                int rr = r + hh * 8;
                int mg = m0 + rr;
                if (mg >= M) continue;
                float v0 = acc[i][j][hh * 2], v1 = acc[i][j][hh * 2 + 1];
                if (ROUTED) {
                    int   slot = base + mg;
                    int   tok  = d_tok[slot];
                    float w    = d_wt[slot];
                    float* op  = Out + (size_t)tok * HDIM + n0 + c;
                    atomicAdd(op,     w * v0);
                    atomicAdd(op + 1, w * v1);
                } else {
                    *(float2*)(Out + (size_t)mg * HDIM + n0 + c) = make_float2(v0, v1);
                }
            }
        }
}

// ---------------- launch ----------------
extern "C" void kernel_launch(void* const* d_in, const int* in_sizes, int n_in,
                              void* d_out, int out_size) {
    const float* x  = (const float*)d_in[0];
    const float* gw = (const float*)d_in[1];
    const float* eg = (const float*)d_in[2];
    const float* eu = (const float*)d_in[3];
    const float* ed = (const float*)d_in[4];
    const float* sg = (const float*)d_in[5];
    const float* su = (const float*)d_in[6];
    const float* sd = (const float*)d_in[7];
    float* out = (float*)d_out;

    __nv_bfloat16 *actHi, *actLo;
    cudaGetSymbolAddress((void**)&actHi, d_actHi);
    cudaGetSymbolAddress((void**)&actLo, d_actLo);

    const int smemGU = 128 * 132 * 4;      // 67584 (>= 6*TILE_BYTES = 61440)
    const int smemDN = 4 * TILE_BYTES;     // 40960
    cudaFuncSetAttribute(gemm_gu<false>, cudaFuncAttributeMaxDynamicSharedMemorySize, smemGU);
    cudaFuncSetAttribute(gemm_gu<true>,  cudaFuncAttributeMaxDynamicSharedMemorySize, smemGU);
    cudaFuncSetAttribute(gemm_down<false>, cudaFuncAttributeMaxDynamicSharedMemorySize, smemDN);
    cudaFuncSetAttribute(gemm_down<true>,  cudaFuncAttributeMaxDynamicSharedMemorySize, smemDN);

    // routing
    zero_kernel<<<1, 32>>>();
    router_kernel<<<N_TOK, 256>>>(x, gw);
    offsets_kernel<<<1, 32>>>();
    scatter_kernel<<<4, 256>>>();

    // shared expert
    gemm_gu<false><<<dim3(ISH / 128, N_TOK / 128, 1), 512, smemGU>>>(
        x, sg, su, actHi, actLo, N_TOK, ISH, HDIM);
    gemm_down<false><<<dim3(HDIM / 128, N_TOK / 128, 1), 512, smemDN>>>(
        actHi, actLo, sd, out, N_TOK, ISH);

    // routed experts
    gemm_gu<true><<<dim3(IDIM / 128, N_TOK / 128, NEXP), 512, smemGU>>>(
        x, eg, eu, actHi, actLo, 0, IDIM, HDIM);
    gemm_down<true><<<dim3(HDIM / 128, N_TOK / 128, NEXP), 512, smemDN>>>(
        actHi, actLo, ed, out, 0, IDIM);
}

// round 6
// speedup vs baseline: 2.0945x; 1.0537x over previous
#include <cuda_runtime.h>
#include <cuda_bf16.h>
#include <math.h>
#include <stdint.h>

#define N_TOK 1024
#define HDIM  2048
#define IDIM  1408
#define NEXP  8
#define ISH   2816
#define NSLOT 2048
#define ACT_ELEMS (2048 * 1408)   // == 1024*2816

#define BK  32                     // k per chunk (elements)
#define LDS 40                     // smem row stride in bf16 (padded)
#define TILE_BYTES (128 * LDS * 2) // 10240

// ---- pre-split weight/x buffer offsets (elements) ----
#define OFF_EG 0ull
#define OFF_EU 23068672ull
#define OFF_ED 46137344ull
#define OFF_SG 69206016ull
#define OFF_SU 74973184ull
#define OFF_SD 80740352ull
#define OFF_X  86507520ull
#define W_TOTAL 88604672ull

// ---------------- scratch (static device memory) ----------------
__device__ int   d_cnt[NEXP];
__device__ int   d_cnt2[NEXP];
__device__ int   d_off[NEXP];
__device__ int   d_sel[N_TOK * 2];
__device__ float d_selw[N_TOK * 2];
__device__ int   d_tok[NSLOT];
__device__ float d_wt[NSLOT];
__device__ __align__(16) __nv_bfloat16 d_actHi[ACT_ELEMS];
__device__ __align__(16) __nv_bfloat16 d_actLo[ACT_ELEMS];
__device__ __align__(16) __nv_bfloat16 d_wHi[W_TOTAL];
__device__ __align__(16) __nv_bfloat16 d_wLo[W_TOTAL];

// ---------------- helpers ----------------
__device__ __forceinline__ uint32_t smem_u32(const void* p) {
    return (uint32_t)__cvta_generic_to_shared(p);
}
__device__ __forceinline__ void cpa16(uint32_t dst, const void* src, uint32_t sz) {
    asm volatile("cp.async.cg.shared.global [%0], [%1], 16, %2;"
                 :: "r"(dst), "l"(src), "r"(sz));
}
__device__ __forceinline__ void cpa_commit() {
    asm volatile("cp.async.commit_group;");
}
__device__ __forceinline__ void cpa_wait1() {
    asm volatile("cp.async.wait_group 1;");
}
__device__ __forceinline__ void cpa_wait0() {
    asm volatile("cp.async.wait_group 0;");
}
__device__ __forceinline__ void ldsm_x4(uint32_t& r0, uint32_t& r1,
                                        uint32_t& r2, uint32_t& r3, uint32_t a) {
    asm volatile("ldmatrix.sync.aligned.m8n8.x4.shared.b16 {%0,%1,%2,%3}, [%4];"
                 : "=r"(r0), "=r"(r1), "=r"(r2), "=r"(r3) : "r"(a));
}
__device__ __forceinline__ void ldsm_x2(uint32_t& r0, uint32_t& r1, uint32_t a) {
    asm volatile("ldmatrix.sync.aligned.m8n8.x2.shared.b16 {%0,%1}, [%2];"
                 : "=r"(r0), "=r"(r1) : "r"(a));
}
__device__ __forceinline__ void mma_bf16(float* c, const uint32_t* a,
                                         const uint32_t* b) {
    asm volatile(
        "mma.sync.aligned.m16n8k16.row.col.f32.bf16.bf16.f32 "
        "{%0,%1,%2,%3}, {%4,%5,%6,%7}, {%8,%9}, {%0,%1,%2,%3};"
        : "+f"(c[0]), "+f"(c[1]), "+f"(c[2]), "+f"(c[3])
        : "r"(a[0]), "r"(a[1]), "r"(a[2]), "r"(a[3]), "r"(b[0]), "r"(b[1]));
}
__device__ __forceinline__ uint32_t bf2u(__nv_bfloat162 v) {
    return *reinterpret_cast<uint32_t*>(&v);
}

// ---------------- split pass: fp32 -> bf16 hi/lo, 8 elems/thread ----------------
__global__ void split_kernel(const float* __restrict__ src,
                             __nv_bfloat16* __restrict__ hi,
                             __nv_bfloat16* __restrict__ lo, int n8) {
    int i = blockIdx.x * blockDim.x + threadIdx.x;
    if (i >= n8) return;
    float4 q0 = ((const float4*)src)[2 * i];
    float4 q1 = ((const float4*)src)[2 * i + 1];
    __nv_bfloat162 h0 = __floats2bfloat162_rn(q0.x, q0.y);
    __nv_bfloat162 h1 = __floats2bfloat162_rn(q0.z, q0.w);
    __nv_bfloat162 h2 = __floats2bfloat162_rn(q1.x, q1.y);
    __nv_bfloat162 h3 = __floats2bfloat162_rn(q1.z, q1.w);
    __nv_bfloat162 l0 = __floats2bfloat162_rn(q0.x - __bfloat162float(h0.x),
                                              q0.y - __bfloat162float(h0.y));
    __nv_bfloat162 l1 = __floats2bfloat162_rn(q0.z - __bfloat162float(h1.x),
                                              q0.w - __bfloat162float(h1.y));
    __nv_bfloat162 l2 = __floats2bfloat162_rn(q1.x - __bfloat162float(h2.x),
                                              q1.y - __bfloat162float(h2.y));
    __nv_bfloat162 l3 = __floats2bfloat162_rn(q1.z - __bfloat162float(h3.x),
                                              q1.w - __bfloat162float(h3.y));
    ((uint4*)hi)[i] = make_uint4(bf2u(h0), bf2u(h1), bf2u(h2), bf2u(h3));
    ((uint4*)lo)[i] = make_uint4(bf2u(l0), bf2u(l1), bf2u(l2), bf2u(l3));
}

// ---------------- small kernels ----------------
__global__ void zero_kernel() {
    int t = threadIdx.x;
    if (t < NEXP) { d_cnt[t] = 0; d_cnt2[t] = 0; }
}

__global__ void router_kernel(const float* __restrict__ x,
                              const float* __restrict__ gw) {
    int n    = blockIdx.x;
    int wid  = threadIdx.x >> 5;
    int lane = threadIdx.x & 31;
    __shared__ float logits[NEXP];
    const float* xr = x  + (size_t)n   * HDIM;
    const float* gr = gw + (size_t)wid * HDIM;
    float s = 0.f;
    for (int h = lane; h < HDIM; h += 32) s = fmaf(xr[h], gr[h], s);
    #pragma unroll
    for (int o = 16; o > 0; o >>= 1) s += __shfl_xor_sync(0xffffffffu, s, o);
    if (lane == 0) logits[wid] = s;
    __syncthreads();
    if (threadIdx.x == 0) {
        float mx = logits[0];
        #pragma unroll
        for (int e = 1; e < NEXP; ++e) mx = fmaxf(mx, logits[e]);
        float p[NEXP]; float sum = 0.f;
        #pragma unroll
        for (int e = 0; e < NEXP; ++e) { p[e] = expf(logits[e] - mx); sum += p[e]; }
        float inv = 1.f / sum;
        #pragma unroll
        for (int e = 0; e < NEXP; ++e) p[e] *= inv;
        float p1 = p[0]; int i1 = 0;
        float p2 = -1.f; int i2 = -1;
        #pragma unroll
        for (int e = 1; e < NEXP; ++e) {
            if (p[e] > p1)      { p2 = p1; i2 = i1; p1 = p[e]; i1 = e; }
            else if (p[e] > p2) { p2 = p[e]; i2 = e; }
        }
        float ws = p1 + p2 + 1e-20f;
        d_sel[n * 2]     = i1; d_selw[n * 2]     = p1 / ws;
        d_sel[n * 2 + 1] = i2; d_selw[n * 2 + 1] = p2 / ws;
        atomicAdd(&d_cnt[i1], 1);
        atomicAdd(&d_cnt[i2], 1);
    }
}

__global__ void offsets_kernel() {
    if (threadIdx.x == 0) {
        int acc = 0;
        #pragma unroll
        for (int e = 0; e < NEXP; ++e) { d_off[e] = acc; acc += d_cnt[e]; }
    }
}

__global__ void scatter_kernel() {
    int n = blockIdx.x * blockDim.x + threadIdx.x;
    if (n >= N_TOK) return;
    #pragma unroll
    for (int k = 0; k < 2; ++k) {
        int   e = d_sel[n * 2 + k];
        float w = d_selw[n * 2 + k];
        int pos  = atomicAdd(&d_cnt2[e], 1);
        int slot = d_off[e] + pos;
        d_tok[slot] = n;
        d_wt[slot]  = w;
    }
}

// ================= GEMM 1: fused gate+up, silu*mul epilogue ====================
// All inputs pre-split bf16 hi/lo. cp.async 2-stage pipeline.
// 512 threads, 16 warps. Warps 0-7: gate tile; warps 8-15: up tile.
template <bool ROUTED>
__global__ __launch_bounds__(512, 1)
void gemm_gu(const __nv_bfloat16* __restrict__ wHi,
             const __nv_bfloat16* __restrict__ wLo,
             size_t offG, size_t offU,
             __nv_bfloat16* __restrict__ actHi,
             __nv_bfloat16* __restrict__ actLo,
             int M, int N, int K)
{
    int e = blockIdx.z, base = 0;
    size_t eoff = 0;
    if (ROUTED) {
        M = d_cnt[e]; base = d_off[e];
        eoff = (size_t)e * N * K;
    }
    int m0 = blockIdx.y * 128;
    if (m0 >= M) return;
    int n0 = blockIdx.x * 128;

    extern __shared__ char smem[];
    uint32_t sb  = smem_u32(smem);
    const uint32_t STG = 6 * TILE_BYTES;
    uint32_t sAh = sb,                  sAl = sb + TILE_BYTES;
    uint32_t sGh = sb + 2 * TILE_BYTES, sGl = sb + 3 * TILE_BYTES;
    uint32_t sUh = sb + 4 * TILE_BYTES, sUl = sb + 5 * TILE_BYTES;
    float* cuS = (float*)smem;          // overlapped exchange region (post-loop)

    int t = threadIdx.x, lane = t & 31, wid = t >> 5;
    int lrow = t >> 2, lcol = (t & 3) * 8;

    bool aval = (m0 + lrow) < M;
    int  arow = ROUTED ? (aval ? d_tok[base + m0 + lrow] : 0)
                       : (aval ? m0 + lrow : 0);
    uint32_t aSz = aval ? 16u : 0u;
    const __nv_bfloat16* ahP = wHi + OFF_X + (size_t)arow * K + lcol;
    const __nv_bfloat16* alP = wLo + OFF_X + (size_t)arow * K + lcol;
    size_t brow = eoff + (size_t)(n0 + lrow) * K + lcol;
    const __nv_bfloat16* ghP = wHi + offG + brow;
    const __nv_bfloat16* glP = wLo + offG + brow;
    const __nv_bfloat16* uhP = wHi + offU + brow;
    const __nv_bfloat16* ulP = wLo + offU + brow;
    uint32_t stO = (uint32_t)(lrow * LDS + lcol) * 2u;

    int  gw   = wid & 7;
    int  wm   = (gw & 1) * 64, wn = (gw >> 1) * 32;
    bool isUp = wid >= 8;
    uint32_t sBh = isUp ? sUh : sGh;
    uint32_t sBl = isUp ? sUl : sGl;

    float acc[4][4][4];
    #pragma unroll
    for (int i = 0; i < 4; ++i)
        #pragma unroll
        for (int j = 0; j < 4; ++j)
            #pragma unroll
            for (int q = 0; q < 4; ++q) acc[i][j][q] = 0.f;

    int KT = K / BK;
    // prologue: stage 0
    {
        cpa16(sAh + stO, ahP, aSz);
        cpa16(sAl + stO, alP, aSz);
        cpa16(sGh + stO, ghP, 16);
        cpa16(sGl + stO, glP, 16);
        cpa16(sUh + stO, uhP, 16);
        cpa16(sUl + stO, ulP, 16);
        cpa_commit();
    }
    for (int ch = 0; ch < KT; ++ch) {
        if (ch + 1 < KT) {
            int k1 = (ch + 1) * BK;
            uint32_t so = ((ch + 1) & 1) ? STG : 0;
            cpa16(sAh + so + stO, ahP + k1, aSz);
            cpa16(sAl + so + stO, alP + k1, aSz);
            cpa16(sGh + so + stO, ghP + k1, 16);
            cpa16(sGl + so + stO, glP + k1, 16);
            cpa16(sUh + so + stO, uhP + k1, 16);
            cpa16(sUl + so + stO, ulP + k1, 16);
            cpa_commit();
            cpa_wait1();
        } else {
            cpa_wait0();
        }
        __syncthreads();
        uint32_t so = (ch & 1) ? STG : 0;
        #pragma unroll
        for (int s = 0; s < 2; ++s) {
            uint32_t bh[4][2], bl[4][2];
            uint32_t bOff = so + (uint32_t)(((wn + (lane & 7)) * LDS
                           + s * 16 + ((lane >> 3) & 1) * 8) * 2);
            #pragma unroll
            for (int j = 0; j < 4; ++j) {
                ldsm_x2(bh[j][0], bh[j][1], sBh + bOff + j * (8 * LDS * 2));
                ldsm_x2(bl[j][0], bl[j][1], sBl + bOff + j * (8 * LDS * 2));
            }
            uint32_t aOff = so + (uint32_t)(((wm + (lane & 15)) * LDS
                           + s * 16 + (lane >> 4) * 8) * 2);
            #pragma unroll
            for (int i = 0; i < 4; ++i) {
                uint32_t ah[4], al[4];
                ldsm_x4(ah[0], ah[1], ah[2], ah[3], sAh + aOff + i * (16 * LDS * 2));
                ldsm_x4(al[0], al[1], al[2], al[3], sAl + aOff + i * (16 * LDS * 2));
                #pragma unroll
                for (int j = 0; j < 4; ++j) {
                    mma_bf16(acc[i][j], ah, bh[j]);
                    mma_bf16(acc[i][j], al, bh[j]);
                    mma_bf16(acc[i][j], ah, bl[j]);
                }
            }
        }
        __syncthreads();
    }

    // exchange: up warps -> smem, gate warps combine + store
    if (isUp) {
        #pragma unroll
        for (int i = 0; i < 4; ++i)
            #pragma unroll
            for (int j = 0; j < 4; ++j) {
                int r = wm + i * 16 + (lane >> 2);
                int c = wn + j * 8 + (lane & 3) * 2;
                *(float2*)&cuS[r * 132 + c]       = make_float2(acc[i][j][0], acc[i][j][1]);
                *(float2*)&cuS[(r + 8) * 132 + c] = make_float2(acc[i][j][2], acc[i][j][3]);
            }
    }
    __syncthreads();
    if (!isUp) {
        #pragma unroll
        for (int i = 0; i < 4; ++i)
            #pragma unroll
            for (int j = 0; j < 4; ++j) {
                int r = wm + i * 16 + (lane >> 2);
                int c = wn + j * 8 + (lane & 3) * 2;
                #pragma unroll
                for (int hh = 0; hh < 2; ++hh) {
                    int rr = r + hh * 8;
                    int mg = m0 + rr;
                    if (mg >= M) continue;
                    float2 uv = *(float2*)&cuS[rr * 132 + c];
                    float g0 = acc[i][j][hh * 2], g1 = acc[i][j][hh * 2 + 1];
                    float a0 = g0 / (1.f + expf(-g0)) * uv.x;
                    float a1 = g1 / (1.f + expf(-g1)) * uv.y;
                    __nv_bfloat162 h = __floats2bfloat162_rn(a0, a1);
                    __nv_bfloat162 l = __floats2bfloat162_rn(
                        a0 - __bfloat162float(h.x), a1 - __bfloat162float(h.y));
                    size_t orow = (size_t)(ROUTED ? base + mg : mg);
                    *(__nv_bfloat162*)(actHi + orow * N + n0 + c) = h;
                    *(__nv_bfloat162*)(actLo + orow * N + n0 + c) = l;
                }
            }
    }
}

// ================= GEMM 2: down projection (N = HDIM) =========================
// A pre-split (act arrays); W pre-split.  cp.async 2-stage pipeline.
template <bool ROUTED>
__global__ __launch_bounds__(512, 1)
void gemm_down(const __nv_bfloat16* __restrict__ AHi,
               const __nv_bfloat16* __restrict__ ALo,
               const __nv_bfloat16* __restrict__ wHi,
               const __nv_bfloat16* __restrict__ wLo,
               size_t offW,
               float* __restrict__ Out,
               int M, int K)
{
    int e = blockIdx.z, base = 0;
    size_t eoff = 0;
    if (ROUTED) {
        M = d_cnt[e]; base = d_off[e];
        eoff = (size_t)e * HDIM * K;
    }
    int m0 = blockIdx.y * 128;
    if (m0 >= M) return;
    int n0 = blockIdx.x * 128;

    extern __shared__ char smem[];
    uint32_t sb  = smem_u32(smem);
    const uint32_t STG = 4 * TILE_BYTES;
    uint32_t sAh = sb,                  sAl = sb + TILE_BYTES;
    uint32_t sBh = sb + 2 * TILE_BYTES, sBl = sb + 3 * TILE_BYTES;

    int t = threadIdx.x, lane = t & 31, wid = t >> 5;
    int lrow = t >> 2, lcol = (t & 3) * 8;

    bool aval = (m0 + lrow) < M;
    uint32_t aSz = aval ? 16u : 0u;
    size_t arow = (size_t)(base + (aval ? m0 + lrow : 0));
    const __nv_bfloat16* ahP = AHi + arow * (size_t)K + lcol;
    const __nv_bfloat16* alP = ALo + arow * (size_t)K + lcol;
    size_t brow = offW + eoff + (size_t)(n0 + lrow) * K + lcol;
    const __nv_bfloat16* bhP = wHi + brow;
    const __nv_bfloat16* blP = wLo + brow;
    uint32_t stO = (uint32_t)(lrow * LDS + lcol) * 2u;

    int wm = (wid & 3) * 32, wn = (wid >> 2) * 32;

    float acc[2][4][4];
    #pragma unroll
    for (int i = 0; i < 2; ++i)
        #pragma unroll
        for (int j = 0; j < 4; ++j)
            #pragma unroll
            for (int q = 0; q < 4; ++q) acc[i][j][q] = 0.f;

    int KT = K / BK;
    {
        cpa16(sAh + stO, ahP, aSz);
        cpa16(sAl + stO, alP, aSz);
        cpa16(sBh + stO, bhP, 16);
        cpa16(sBl + stO, blP, 16);
        cpa_commit();
    }
    for (int ch = 0; ch < KT; ++ch) {
        if (ch + 1 < KT) {
            int k1 = (ch + 1) * BK;
            uint32_t so = ((ch + 1) & 1) ? STG : 0;
            cpa16(sAh + so + stO, ahP + k1, aSz);
            cpa16(sAl + so + stO, alP + k1, aSz);
            cpa16(sBh + so + stO, bhP + k1, 16);
            cpa16(sBl + so + stO, blP + k1, 16);
            cpa_commit();
            cpa_wait1();
        } else {
            cpa_wait0();
        }
        __syncthreads();
        uint32_t so = (ch & 1) ? STG : 0;
        #pragma unroll
        for (int s = 0; s < 2; ++s) {
            uint32_t bh[4][2], bl[4][2];
            uint32_t bOff = so + (uint32_t)(((wn + (lane & 7)) * LDS
                           + s * 16 + ((lane >> 3) & 1) * 8) * 2);
            #pragma unroll
            for (int j = 0; j < 4; ++j) {
                ldsm_x2(bh[j][0], bh[j][1], sBh + bOff + j * (8 * LDS * 2));
                ldsm_x2(bl[j][0], bl[j][1], sBl + bOff + j * (8 * LDS * 2));
            }
            uint32_t aOff = so + (uint32_t)(((wm + (lane & 15)) * LDS
                           + s * 16 + (lane >> 4) * 8) * 2);
            #pragma unroll
            for (int i = 0; i < 2; ++i) {
                uint32_t ah[4], al[4];
                ldsm_x4(ah[0], ah[1], ah[2], ah[3], sAh + aOff + i * (16 * LDS * 2));
                ldsm_x4(al[0], al[1], al[2], al[3], sAl + aOff + i * (16 * LDS * 2));
                #pragma unroll
                for (int j = 0; j < 4; ++j) {
                    mma_bf16(acc[i][j], ah, bh[j]);
                    mma_bf16(acc[i][j], al, bh[j]);
                    mma_bf16(acc[i][j], ah, bl[j]);
                }
            }
        }
        __syncthreads();
    }

    #pragma unroll
    for (int i = 0; i < 2; ++i)
        #pragma unroll
        for (int j = 0; j < 4; ++j) {
            int r = wm + i * 16 + (lane >> 2);
            int c = wn + j * 8 + (lane & 3) * 2;
            #pragma unroll
            for (int hh = 0; hh < 2; ++hh) {
                int rr = r + hh * 8;
                int mg = m0 + rr;
                if (mg >= M) continue;
                float v0 = acc[i][j][hh * 2], v1 = acc[i][j][hh * 2 + 1];
                if (ROUTED) {
                    int   slot = base + mg;
                    int   tok  = d_tok[slot];
                    float w    = d_wt[slot];
                    float* op  = Out + (size_t)tok * HDIM + n0 + c;
                    atomicAdd(op,     w * v0);
                    atomicAdd(op + 1, w * v1);
                } else {
                    *(float2*)(Out + (size_t)mg * HDIM + n0 + c) = make_float2(v0, v1);
                }
            }
        }
}

// ---------------- launch ----------------
extern "C" void kernel_launch(void* const* d_in, const int* in_sizes, int n_in,
                              void* d_out, int out_size) {
    const float* x  = (const float*)d_in[0];
    const float* gw = (const float*)d_in[1];
    const float* eg = (const float*)d_in[2];
    const float* eu = (const float*)d_in[3];
    const float* ed = (const float*)d_in[4];
    const float* sg = (const float*)d_in[5];
    const float* su = (const float*)d_in[6];
    const float* sd = (const float*)d_in[7];
    float* out = (float*)d_out;

    __nv_bfloat16 *actHi, *actLo, *wHi, *wLo;
    cudaGetSymbolAddress((void**)&actHi, d_actHi);
    cudaGetSymbolAddress((void**)&actLo, d_actLo);
    cudaGetSymbolAddress((void**)&wHi, d_wHi);
    cudaGetSymbolAddress((void**)&wLo, d_wLo);

    const int smemGU = 12 * TILE_BYTES;    // 122880
    const int smemDN = 8 * TILE_BYTES;     // 81920
    cudaFuncSetAttribute(gemm_gu<false>, cudaFuncAttributeMaxDynamicSharedMemorySize, smemGU);
    cudaFuncSetAttribute(gemm_gu<true>,  cudaFuncAttributeMaxDynamicSharedMemorySize, smemGU);
    cudaFuncSetAttribute(gemm_down<false>, cudaFuncAttributeMaxDynamicSharedMemorySize, smemDN);
    cudaFuncSetAttribute(gemm_down<true>,  cudaFuncAttributeMaxDynamicSharedMemorySize, smemDN);

    // routing
    zero_kernel<<<1, 32>>>();
    router_kernel<<<N_TOK, 256>>>(x, gw);
    offsets_kernel<<<1, 32>>>();
    scatter_kernel<<<4, 256>>>();

    // pre-split all operands to bf16 hi/lo
    auto split = [&](const float* src, size_t off, size_t n) {
        int n8 = (int)(n / 8);
        split_kernel<<<(n8 + 255) / 256, 256>>>(src, wHi + off, wLo + off, n8);
    };
    split(eg, OFF_EG, (size_t)NEXP * IDIM * HDIM);
    split(eu, OFF_EU, (size_t)NEXP * IDIM * HDIM);
    split(ed, OFF_ED, (size_t)NEXP * HDIM * IDIM);
    split(sg, OFF_SG, (size_t)ISH * HDIM);
    split(su, OFF_SU, (size_t)ISH * HDIM);
    split(sd, OFF_SD, (size_t)HDIM * ISH);
    split(x,  OFF_X,  (size_t)N_TOK * HDIM);

    // shared expert
    gemm_gu<false><<<dim3(ISH / 128, N_TOK / 128, 1), 512, smemGU>>>(
        wHi, wLo, OFF_SG, OFF_SU, actHi, actLo, N_TOK, ISH, HDIM);
    gemm_down<false><<<dim3(HDIM / 128, N_TOK / 128, 1), 512, smemDN>>>(
        actHi, actLo, wHi, wLo, OFF_SD, out, N_TOK, ISH);

    // routed experts
    gemm_gu<true><<<dim3(IDIM / 128, N_TOK / 128, NEXP), 512, smemGU>>>(
        wHi, wLo, OFF_EG, OFF_EU, actHi, actLo, 0, IDIM, HDIM);
    gemm_down<true><<<dim3(HDIM / 128, N_TOK / 128, NEXP), 512, smemDN>>>(
        actHi, actLo, wHi, wLo, OFF_ED, out, 0, IDIM);
}

// round 7
// speedup vs baseline: 2.8937x; 1.3816x over previous
#include <cuda_runtime.h>
#include <cuda_fp16.h>
#include <math.h>
#include <stdint.h>

#define N_TOK 1024
#define HDIM  2048
#define IDIM  1408
#define NEXP  8
#define ISH   2816
#define NSLOT 2048
#define ACT_ELEMS (2048 * 1408)   // == 1024*2816

#define BK   32
#define LDS  40                    // smem row stride in halves (padded)
#define TILE 10240                 // 128 rows * 40 halves * 2B
#define NSTG 3
#define SMEM_GEMM (NSTG * 3 * TILE)  // 92160

// ---- fp16 weight buffer offsets (elements) ----
#define OFF_EG 0ull
#define OFF_EU 23068672ull
#define OFF_ED 46137344ull
#define OFF_SG 69206016ull
#define OFF_SU 74973184ull
#define OFF_SD 80740352ull
#define W_TOTAL 86507520ull

// ---------------- scratch (static device memory) ----------------
__device__ int   d_cnt[NEXP];
__device__ int   d_cnt2[NEXP];
__device__ int   d_off[NEXP];
__device__ int   d_sel[N_TOK * 2];
__device__ float d_selw[N_TOK * 2];
__device__ int   d_tok[NSLOT];
__device__ float d_wt[NSLOT];
__device__ __align__(16) __half d_wH[W_TOTAL];
__device__ __align__(16) __half d_xHi[N_TOK * HDIM];
__device__ __align__(16) __half d_xLo[N_TOK * HDIM];
__device__ __align__(16) __half d_actHi[ACT_ELEMS];
__device__ __align__(16) __half d_actLo[ACT_ELEMS];
__device__ __align__(16) float  d_gbuf[ACT_ELEMS];

// ---------------- helpers ----------------
__device__ __forceinline__ uint32_t smem_u32(const void* p) {
    return (uint32_t)__cvta_generic_to_shared(p);
}
__device__ __forceinline__ void cpa16(uint32_t dst, const void* src, uint32_t sz) {
    asm volatile("cp.async.cg.shared.global [%0], [%1], 16, %2;"
                 :: "r"(dst), "l"(src), "r"(sz));
}
__device__ __forceinline__ void cpa_commit() {
    asm volatile("cp.async.commit_group;");
}
__device__ __forceinline__ void cpa_wait1() {
    asm volatile("cp.async.wait_group 1;");
}
__device__ __forceinline__ void ldsm_x4(uint32_t& r0, uint32_t& r1,
                                        uint32_t& r2, uint32_t& r3, uint32_t a) {
    asm volatile("ldmatrix.sync.aligned.m8n8.x4.shared.b16 {%0,%1,%2,%3}, [%4];"
                 : "=r"(r0), "=r"(r1), "=r"(r2), "=r"(r3) : "r"(a));
}
__device__ __forceinline__ void mma_f16(float* c, const uint32_t* a,
                                        const uint32_t* b) {
    asm volatile(
        "mma.sync.aligned.m16n8k16.row.col.f32.f16.f16.f32 "
        "{%0,%1,%2,%3}, {%4,%5,%6,%7}, {%8,%9}, {%0,%1,%2,%3};"
        : "+f"(c[0]), "+f"(c[1]), "+f"(c[2]), "+f"(c[3])
        : "r"(a[0]), "r"(a[1]), "r"(a[2]), "r"(a[3]), "r"(b[0]), "r"(b[1]));
}
__device__ __forceinline__ uint32_t h2u(__half2 v) {
    return *reinterpret_cast<uint32_t*>(&v);
}

// ---------------- split kernels ----------------
// weights: fp32 -> fp16 (single), 8 elems/thread
__global__ void split_w_kernel(const float* __restrict__ src,
                               __half* __restrict__ dst, int n8) {
    int i = blockIdx.x * blockDim.x + threadIdx.x;
    if (i >= n8) return;
    float4 q0 = ((const float4*)src)[2 * i];
    float4 q1 = ((const float4*)src)[2 * i + 1];
    __half2 h0 = __floats2half2_rn(q0.x, q0.y);
    __half2 h1 = __floats2half2_rn(q0.z, q0.w);
    __half2 h2 = __floats2half2_rn(q1.x, q1.y);
    __half2 h3 = __floats2half2_rn(q1.z, q1.w);
    ((uint4*)dst)[i] = make_uint4(h2u(h0), h2u(h1), h2u(h2), h2u(h3));
}
// x: fp32 -> fp16 hi + lo
__global__ void split_x_kernel(const float* __restrict__ src,
                               __half* __restrict__ hi,
                               __half* __restrict__ lo, int n8) {
    int i = blockIdx.x * blockDim.x + threadIdx.x;
    if (i >= n8) return;
    float4 q0 = ((const float4*)src)[2 * i];
    float4 q1 = ((const float4*)src)[2 * i + 1];
    __half2 h0 = __floats2half2_rn(q0.x, q0.y);
    __half2 h1 = __floats2half2_rn(q0.z, q0.w);
    __half2 h2 = __floats2half2_rn(q1.x, q1.y);
    __half2 h3 = __floats2half2_rn(q1.z, q1.w);
    __half2 l0 = __floats2half2_rn(q0.x - __low2float(h0), q0.y - __high2float(h0));
    __half2 l1 = __floats2half2_rn(q0.z - __low2float(h1), q0.w - __high2float(h1));
    __half2 l2 = __floats2half2_rn(q1.x - __low2float(h2), q1.y - __high2float(h2));
    __half2 l3 = __floats2half2_rn(q1.z - __low2float(h3), q1.w - __high2float(h3));
    ((uint4*)hi)[i] = make_uint4(h2u(h0), h2u(h1), h2u(h2), h2u(h3));
    ((uint4*)lo)[i] = make_uint4(h2u(l0), h2u(l1), h2u(l2), h2u(l3));
}

// ---------------- routing kernels ----------------
__global__ void zero_kernel() {
    int t = threadIdx.x;
    if (t < NEXP) { d_cnt[t] = 0; d_cnt2[t] = 0; }
}

__global__ void router_kernel(const float* __restrict__ x,
                              const float* __restrict__ gw) {
    int n    = blockIdx.x;
    int wid  = threadIdx.x >> 5;
    int lane = threadIdx.x & 31;
    __shared__ float logits[NEXP];
    const float* xr = x  + (size_t)n   * HDIM;
    const float* gr = gw + (size_t)wid * HDIM;
    float s = 0.f;
    for (int h = lane; h < HDIM; h += 32) s = fmaf(xr[h], gr[h], s);
    #pragma unroll
    for (int o = 16; o > 0; o >>= 1) s += __shfl_xor_sync(0xffffffffu, s, o);
    if (lane == 0) logits[wid] = s;
    __syncthreads();
    if (threadIdx.x == 0) {
        float mx = logits[0];
        #pragma unroll
        for (int e = 1; e < NEXP; ++e) mx = fmaxf(mx, logits[e]);
        float p[NEXP]; float sum = 0.f;
        #pragma unroll
        for (int e = 0; e < NEXP; ++e) { p[e] = expf(logits[e] - mx); sum += p[e]; }
        float inv = 1.f / sum;
        #pragma unroll
        for (int e = 0; e < NEXP; ++e) p[e] *= inv;
        float p1 = p[0]; int i1 = 0;
        float p2 = -1.f; int i2 = -1;
        #pragma unroll
        for (int e = 1; e < NEXP; ++e) {
            if (p[e] > p1)      { p2 = p1; i2 = i1; p1 = p[e]; i1 = e; }
            else if (p[e] > p2) { p2 = p[e]; i2 = e; }
        }
        float ws = p1 + p2 + 1e-20f;
        d_sel[n * 2]     = i1; d_selw[n * 2]     = p1 / ws;
        d_sel[n * 2 + 1] = i2; d_selw[n * 2 + 1] = p2 / ws;
        atomicAdd(&d_cnt[i1], 1);
        atomicAdd(&d_cnt[i2], 1);
    }
}

__global__ void offsets_kernel() {
    if (threadIdx.x == 0) {
        int acc = 0;
        #pragma unroll
        for (int e = 0; e < NEXP; ++e) { d_off[e] = acc; acc += d_cnt[e]; }
    }
}

__global__ void scatter_kernel() {
    int n = blockIdx.x * blockDim.x + threadIdx.x;
    if (n >= N_TOK) return;
    #pragma unroll
    for (int k = 0; k < 2; ++k) {
        int   e = d_sel[n * 2 + k];
        float w = d_selw[n * 2 + k];
        int pos  = atomicAdd(&d_cnt2[e], 1);
        int slot = d_off[e] + pos;
        d_tok[slot] = n;
        d_wt[slot]  = w;
    }
}

// ================= unified GEMM: C[m,n] = sum_k A[m,k]*B[n,k] ==================
// A = (AHi + ALo) fp16 2-term; B = single fp16 weights.
// EPI 0: store fp32 to Fout (gbuf), row = slot/token          (gate)
// EPI 1: u = acc; g = gIn; act = silu(g)*u -> fp16 hi/lo split (up)
// EPI 2: store fp32 to Fout, row = m (final out, shared down)
// EPI 3: atomicAdd(Fout[tok], wt*acc)     (routed down)
// ROUTED: blockIdx.z = expert; EPI<=1 gathers A rows via d_tok; EPI>=2 A rows = slots.
template <int EPI, bool ROUTED>
__global__ __launch_bounds__(256, 2)
void gemm(const __half* __restrict__ W, size_t offB,
          const __half* __restrict__ AHi, const __half* __restrict__ ALo,
          float* __restrict__ Fout,
          __half* __restrict__ actH, __half* __restrict__ actL,
          const float* __restrict__ gIn,
          int M, int N, int K)
{
    int e = blockIdx.z, base = 0;
    size_t eoff = 0;
    if (ROUTED) {
        M = d_cnt[e]; base = d_off[e];
        eoff = (size_t)e * (size_t)N * (size_t)K;
    }
    int m0 = blockIdx.y * 128;
    if (m0 >= M) return;
    int n0 = blockIdx.x * 128;

    extern __shared__ char smem[];
    uint32_t sb = smem_u32(smem);

    int t = threadIdx.x, lane = t & 31, wid = t >> 5;

    // ---- loader mapping: thread t -> row t>>1, cols (t&1)*16 + {0,8} ----
    int lr = t >> 1;
    int lc = (t & 1) * 16;
    bool av = (m0 + lr) < M;
    uint32_t aSz = av ? 16u : 0u;
    int arow;
    if (EPI <= 1) arow = ROUTED ? (av ? d_tok[base + m0 + lr] : 0)
                                : (av ? m0 + lr : 0);
    else          arow = base + (av ? m0 + lr : 0);
    const __half* aPh = AHi + (size_t)arow * K + lc;
    const __half* aPl = ALo + (size_t)arow * K + lc;
    const __half* bP  = W + offB + eoff + (size_t)(n0 + lr) * K + lc;
    uint32_t stOff = (uint32_t)(lr * LDS + lc) * 2u;

    int wm = (wid & 3) * 32;
    int wn = (wid >> 2) * 64;

    float acc[2][8][4];
    #pragma unroll
    for (int i = 0; i < 2; ++i)
        #pragma unroll
        for (int j = 0; j < 8; ++j)
            #pragma unroll
            for (int q = 0; q < 4; ++q) acc[i][j][q] = 0.f;

    int KT = K / BK;
    // prologue: stages 0,1
    #pragma unroll
    for (int p = 0; p < 2; ++p) {
        uint32_t s0 = sb + p * 3 * TILE;
        int k0 = p * BK;
        cpa16(s0 + stOff,                aPh + k0,     aSz);
        cpa16(s0 + stOff + 16,           aPh + k0 + 8, aSz);
        cpa16(s0 + TILE + stOff,         aPl + k0,     aSz);
        cpa16(s0 + TILE + stOff + 16,    aPl + k0 + 8, aSz);
        cpa16(s0 + 2 * TILE + stOff,     bP + k0,      16);
        cpa16(s0 + 2 * TILE + stOff + 16, bP + k0 + 8, 16);
        cpa_commit();
    }

    for (int ch = 0; ch < KT; ++ch) {
        cpa_wait1();
        __syncthreads();
        if (ch + 2 < KT) {
            int stg = (ch + 2) % NSTG;
            uint32_t s0 = sb + stg * 3 * TILE;
            int k0 = (ch + 2) * BK;
            cpa16(s0 + stOff,                aPh + k0,     aSz);
            cpa16(s0 + stOff + 16,           aPh + k0 + 8, aSz);
            cpa16(s0 + TILE + stOff,         aPl + k0,     aSz);
            cpa16(s0 + TILE + stOff + 16,    aPl + k0 + 8, aSz);
            cpa16(s0 + 2 * TILE + stOff,     bP + k0,      16);
            cpa16(s0 + 2 * TILE + stOff + 16, bP + k0 + 8, 16);
        }
        cpa_commit();

        uint32_t cs  = sb + (ch % NSTG) * 3 * TILE;
        uint32_t sAh = cs, sAl = cs + TILE, sBB = cs + 2 * TILE;
        #pragma unroll
        for (int s = 0; s < 2; ++s) {
            uint32_t b[8][2];
            #pragma unroll
            for (int jj = 0; jj < 4; ++jj) {
                uint32_t addr = sBB + (uint32_t)(((wn + jj * 16 + (lane & 7)
                              + ((lane >> 4) & 1) * 8) * LDS
                              + s * 16 + ((lane >> 3) & 1) * 8) * 2);
                ldsm_x4(b[2 * jj][0], b[2 * jj][1],
                        b[2 * jj + 1][0], b[2 * jj + 1][1], addr);
            }
            #pragma unroll
            for (int i = 0; i < 2; ++i) {
                uint32_t aOff = (uint32_t)(((wm + i * 16 + (lane & 15)) * LDS
                              + s * 16 + (lane >> 4) * 8) * 2);
                uint32_t ah[4], al[4];
                ldsm_x4(ah[0], ah[1], ah[2], ah[3], sAh + aOff);
                ldsm_x4(al[0], al[1], al[2], al[3], sAl + aOff);
                #pragma unroll
                for (int j = 0; j < 8; ++j) {
                    mma_f16(acc[i][j], ah, b[j]);
                    mma_f16(acc[i][j], al, b[j]);
                }
            }
        }
    }

    // ---- epilogue ----
    #pragma unroll
    for (int i = 0; i < 2; ++i) {
        #pragma unroll
        for (int hh = 0; hh < 2; ++hh) {
            int r  = wm + i * 16 + (lane >> 2) + hh * 8;
            int mg = m0 + r;
            if (mg >= M) continue;
            if (EPI == 0) {
                size_t orow = (size_t)(ROUTED ? base + mg : mg);
                float* op = Fout + orow * (size_t)N + n0;
                #pragma unroll
                for (int j = 0; j < 8; ++j) {
                    int c = wn + j * 8 + (lane & 3) * 2;
                    *(float2*)(op + c) = make_float2(acc[i][j][hh * 2],
                                                     acc[i][j][hh * 2 + 1]);
                }
            } else if (EPI == 1) {
                size_t orow = (size_t)(ROUTED ? base + mg : mg);
                const float* gp = gIn + orow * (size_t)N + n0;
                __half* ph = actH + orow * (size_t)N + n0;
                __half* pl = actL + orow * (size_t)N + n0;
                #pragma unroll
                for (int j = 0; j < 8; ++j) {
                    int c = wn + j * 8 + (lane & 3) * 2;
                    float2 g2 = *(const float2*)(gp + c);
                    float u0 = acc[i][j][hh * 2], u1 = acc[i][j][hh * 2 + 1];
                    float a0 = g2.x / (1.f + expf(-g2.x)) * u0;
                    float a1 = g2.y / (1.f + expf(-g2.y)) * u1;
                    __half2 h = __floats2half2_rn(a0, a1);
                    __half2 l = __floats2half2_rn(a0 - __low2float(h),
                                                  a1 - __high2float(h));
                    *(__half2*)(ph + c) = h;
                    *(__half2*)(pl + c) = l;
                }
            } else if (EPI == 2) {
                float* op = Fout + (size_t)mg * HDIM + n0;
                #pragma unroll
                for (int j = 0; j < 8; ++j) {
                    int c = wn + j * 8 + (lane & 3) * 2;
                    *(float2*)(op + c) = make_float2(acc[i][j][hh * 2],
                                                     acc[i][j][hh * 2 + 1]);
                }
            } else {
                int   slot = base + mg;
                int   tok  = d_tok[slot];
                float w    = d_wt[slot];
                float* op  = Fout + (size_t)tok * HDIM + n0;
                #pragma unroll
                for (int j = 0; j < 8; ++j) {
                    int c = wn + j * 8 + (lane & 3) * 2;
                    atomicAdd(op + c,     w * acc[i][j][hh * 2]);
                    atomicAdd(op + c + 1, w * acc[i][j][hh * 2 + 1]);
                }
            }
        }
    }
}

// ---------------- launch ----------------
extern "C" void kernel_launch(void* const* d_in, const int* in_sizes, int n_in,
                              void* d_out, int out_size) {
    const float* x  = (const float*)d_in[0];
    const float* gw = (const float*)d_in[1];
    const float* eg = (const float*)d_in[2];
    const float* eu = (const float*)d_in[3];
    const float* ed = (const float*)d_in[4];
    const float* sg = (const float*)d_in[5];
    const float* su = (const float*)d_in[6];
    const float* sd = (const float*)d_in[7];
    float* out = (float*)d_out;

    __half *wH, *xHi, *xLo, *actH, *actL;
    float* gbuf;
    cudaGetSymbolAddress((void**)&wH,   d_wH);
    cudaGetSymbolAddress((void**)&xHi,  d_xHi);
    cudaGetSymbolAddress((void**)&xLo,  d_xLo);
    cudaGetSymbolAddress((void**)&actH, d_actHi);
    cudaGetSymbolAddress((void**)&actL, d_actLo);
    cudaGetSymbolAddress((void**)&gbuf, d_gbuf);

    cudaFuncSetAttribute(gemm<0,false>, cudaFuncAttributeMaxDynamicSharedMemorySize, SMEM_GEMM);
    cudaFuncSetAttribute(gemm<1,false>, cudaFuncAttributeMaxDynamicSharedMemorySize, SMEM_GEMM);
    cudaFuncSetAttribute(gemm<2,false>, cudaFuncAttributeMaxDynamicSharedMemorySize, SMEM_GEMM);
    cudaFuncSetAttribute(gemm<0,true>,  cudaFuncAttributeMaxDynamicSharedMemorySize, SMEM_GEMM);
    cudaFuncSetAttribute(gemm<1,true>,  cudaFuncAttributeMaxDynamicSharedMemorySize, SMEM_GEMM);
    cudaFuncSetAttribute(gemm<3,true>,  cudaFuncAttributeMaxDynamicSharedMemorySize, SMEM_GEMM);

    // routing
    zero_kernel<<<1, 32>>>();
    router_kernel<<<N_TOK, 256>>>(x, gw);
    offsets_kernel<<<1, 32>>>();
    scatter_kernel<<<4, 256>>>();

    // conversions
    auto splitw = [&](const float* src, size_t off, size_t n) {
        int n8 = (int)(n / 8);
        split_w_kernel<<<(n8 + 255) / 256, 256>>>(src, wH + off, n8);
    };
    splitw(eg, OFF_EG, (size_t)NEXP * IDIM * HDIM);
    splitw(eu, OFF_EU, (size_t)NEXP * IDIM * HDIM);
    splitw(ed, OFF_ED, (size_t)NEXP * HDIM * IDIM);
    splitw(sg, OFF_SG, (size_t)ISH * HDIM);
    splitw(su, OFF_SU, (size_t)ISH * HDIM);
    splitw(sd, OFF_SD, (size_t)HDIM * ISH);
    {
        int n8 = (N_TOK * HDIM) / 8;
        split_x_kernel<<<(n8 + 255) / 256, 256>>>(x, xHi, xLo, n8);
    }

    // shared expert: gate -> gbuf, up+silu -> act, down -> out (initializes out)
    gemm<0,false><<<dim3(ISH / 128, N_TOK / 128, 1), 256, SMEM_GEMM>>>(
        wH, OFF_SG, xHi, xLo, gbuf, nullptr, nullptr, nullptr, N_TOK, ISH, HDIM);
    gemm<1,false><<<dim3(ISH / 128, N_TOK / 128, 1), 256, SMEM_GEMM>>>(
        wH, OFF_SU, xHi, xLo, nullptr, actH, actL, gbuf, N_TOK, ISH, HDIM);
    gemm<2,false><<<dim3(HDIM / 128, N_TOK / 128, 1), 256, SMEM_GEMM>>>(
        wH, OFF_SD, actH, actL, out, nullptr, nullptr, nullptr, N_TOK, HDIM, ISH);

    // routed experts
    gemm<0,true><<<dim3(IDIM / 128, N_TOK / 128, NEXP), 256, SMEM_GEMM>>>(
        wH, OFF_EG, xHi, xLo, gbuf, nullptr, nullptr, nullptr, 0, IDIM, HDIM);
    gemm<1,true><<<dim3(IDIM / 128, N_TOK / 128, NEXP), 256, SMEM_GEMM>>>(
        wH, OFF_EU, xHi, xLo, nullptr, actH, actL, gbuf, 0, IDIM, HDIM);
    gemm<3,true><<<dim3(HDIM / 128, N_TOK / 128, NEXP), 256, SMEM_GEMM>>>(
        wH, OFF_ED, actH, actL, out, nullptr, nullptr, nullptr, 0, HDIM, IDIM);
}

// round 8
// speedup vs baseline: 4.3924x; 1.5179x over previous
#include <cuda_runtime.h>
#include <cuda_fp16.h>
#include <math.h>
#include <stdint.h>

#define N_TOK 1024
#define HDIM  2048
#define IDIM  1408
#define NEXP  8
#define ISH   2816
#define NSLOT 2048
#define ACT_ELEMS (2048 * 1408)   // == 1024*2816

#define BK   32
#define LDS  40                    // smem row stride in halves (padded)
#define TILE 10240                 // 128 rows * 40 halves * 2B
#define NSTG 4
#define SMEM_GEMM (NSTG * 2 * TILE)  // 81920

// ---- fp16 weight buffer offsets (elements) ----
#define OFF_EG 0ull
#define OFF_EU 23068672ull
#define OFF_ED 46137344ull
#define OFF_SG 69206016ull
#define OFF_SU 74973184ull
#define OFF_SD 80740352ull
#define W_TOTAL 86507520ull

// ---------------- scratch (static device memory) ----------------
__device__ int   d_cnt[NEXP];
__device__ int   d_cnt2[NEXP];
__device__ int   d_off[NEXP];
__device__ int   d_sel[N_TOK * 2];
__device__ float d_selw[N_TOK * 2];
__device__ int   d_tok[NSLOT];
__device__ float d_wt[NSLOT];
__device__ __align__(16) __half d_wH[W_TOTAL];
__device__ __align__(16) __half d_xH[N_TOK * HDIM];
__device__ __align__(16) __half d_actH[ACT_ELEMS];
__device__ __align__(16) float  d_gbuf[ACT_ELEMS];

// ---------------- helpers ----------------
__device__ __forceinline__ uint32_t smem_u32(const void* p) {
    return (uint32_t)__cvta_generic_to_shared(p);
}
__device__ __forceinline__ void cpa16(uint32_t dst, const void* src, uint32_t sz) {
    asm volatile("cp.async.cg.shared.global [%0], [%1], 16, %2;"
                 :: "r"(dst), "l"(src), "r"(sz));
}
__device__ __forceinline__ void cpa_commit() {
    asm volatile("cp.async.commit_group;");
}
__device__ __forceinline__ void cpa_wait2() {
    asm volatile("cp.async.wait_group 2;");
}
__device__ __forceinline__ void ldsm_x4(uint32_t& r0, uint32_t& r1,
                                        uint32_t& r2, uint32_t& r3, uint32_t a) {
    asm volatile("ldmatrix.sync.aligned.m8n8.x4.shared.b16 {%0,%1,%2,%3}, [%4];"
                 : "=r"(r0), "=r"(r1), "=r"(r2), "=r"(r3) : "r"(a));
}
__device__ __forceinline__ void mma_f16(float* c, const uint32_t* a,
                                        const uint32_t* b) {
    asm volatile(
        "mma.sync.aligned.m16n8k16.row.col.f32.f16.f16.f32 "
        "{%0,%1,%2,%3}, {%4,%5,%6,%7}, {%8,%9}, {%0,%1,%2,%3};"
        : "+f"(c[0]), "+f"(c[1]), "+f"(c[2]), "+f"(c[3])
        : "r"(a[0]), "r"(a[1]), "r"(a[2]), "r"(a[3]), "r"(b[0]), "r"(b[1]));
}
__device__ __forceinline__ uint32_t h2u(__half2 v) {
    return *reinterpret_cast<uint32_t*>(&v);
}

// ---------------- conversion: fp32 -> fp16, 8 elems/thread ----------------
__global__ void cvt_h_kernel(const float* __restrict__ src,
                             __half* __restrict__ dst, int n8) {
    int i = blockIdx.x * blockDim.x + threadIdx.x;
    if (i >= n8) return;
    float4 q0 = ((const float4*)src)[2 * i];
    float4 q1 = ((const float4*)src)[2 * i + 1];
    __half2 h0 = __floats2half2_rn(q0.x, q0.y);
    __half2 h1 = __floats2half2_rn(q0.z, q0.w);
    __half2 h2 = __floats2half2_rn(q1.x, q1.y);
    __half2 h3 = __floats2half2_rn(q1.z, q1.w);
    ((uint4*)dst)[i] = make_uint4(h2u(h0), h2u(h1), h2u(h2), h2u(h3));
}

// ---------------- routing kernels ----------------
__global__ void zero_kernel() {
    int t = threadIdx.x;
    if (t < NEXP) { d_cnt[t] = 0; d_cnt2[t] = 0; }
}

__global__ void router_kernel(const float* __restrict__ x,
                              const float* __restrict__ gw) {
    int n    = blockIdx.x;
    int wid  = threadIdx.x >> 5;
    int lane = threadIdx.x & 31;
    __shared__ float logits[NEXP];
    const float* xr = x  + (size_t)n   * HDIM;
    const float* gr = gw + (size_t)wid * HDIM;
    float s = 0.f;
    for (int h = lane; h < HDIM; h += 32) s = fmaf(xr[h], gr[h], s);
    #pragma unroll
    for (int o = 16; o > 0; o >>= 1) s += __shfl_xor_sync(0xffffffffu, s, o);
    if (lane == 0) logits[wid] = s;
    __syncthreads();
    if (threadIdx.x == 0) {
        float mx = logits[0];
        #pragma unroll
        for (int e = 1; e < NEXP; ++e) mx = fmaxf(mx, logits[e]);
        float p[NEXP]; float sum = 0.f;
        #pragma unroll
        for (int e = 0; e < NEXP; ++e) { p[e] = expf(logits[e] - mx); sum += p[e]; }
        float inv = 1.f / sum;
        #pragma unroll
        for (int e = 0; e < NEXP; ++e) p[e] *= inv;
        float p1 = p[0]; int i1 = 0;
        float p2 = -1.f; int i2 = -1;
        #pragma unroll
        for (int e = 1; e < NEXP; ++e) {
            if (p[e] > p1)      { p2 = p1; i2 = i1; p1 = p[e]; i1 = e; }
            else if (p[e] > p2) { p2 = p[e]; i2 = e; }
        }
        float ws = p1 + p2 + 1e-20f;
        d_sel[n * 2]     = i1; d_selw[n * 2]     = p1 / ws;
        d_sel[n * 2 + 1] = i2; d_selw[n * 2 + 1] = p2 / ws;
        atomicAdd(&d_cnt[i1], 1);
        atomicAdd(&d_cnt[i2], 1);
    }
}

__global__ void offsets_kernel() {
    if (threadIdx.x == 0) {
        int acc = 0;
        #pragma unroll
        for (int e = 0; e < NEXP; ++e) { d_off[e] = acc; acc += d_cnt[e]; }
    }
}

__global__ void scatter_kernel() {
    int n = blockIdx.x * blockDim.x + threadIdx.x;
    if (n >= N_TOK) return;
    #pragma unroll
    for (int k = 0; k < 2; ++k) {
        int   e = d_sel[n * 2 + k];
        float w = d_selw[n * 2 + k];
        int pos  = atomicAdd(&d_cnt2[e], 1);
        int slot = d_off[e] + pos;
        d_tok[slot] = n;
        d_wt[slot]  = w;
    }
}

// ================= unified GEMM: C[m,n] = sum_k A[m,k]*B[n,k] ==================
// A, B single fp16.
// EPI 0: store fp32 to Fout (gbuf), row = slot/token           (gate)
// EPI 1: u = acc; g = gIn; act = silu(g)*u -> fp16              (up)
// EPI 2: store fp32 to Fout, row = m (final out, shared down)
// EPI 3: atomicAdd(Fout[tok], wt*acc)      (routed down)
// ROUTED: blockIdx.z = expert; EPI<=1 gathers A rows via d_tok; EPI>=2 A rows = slots.
template <int EPI, bool ROUTED>
__global__ __launch_bounds__(256, 2)
void gemm(const __half* __restrict__ W, size_t offB,
          const __half* __restrict__ A,
          float* __restrict__ Fout,
          __half* __restrict__ actH,
          const float* __restrict__ gIn,
          int M, int N, int K)
{
    int e = blockIdx.z, base = 0;
    size_t eoff = 0;
    if (ROUTED) {
        M = d_cnt[e]; base = d_off[e];
        eoff = (size_t)e * (size_t)N * (size_t)K;
    }
    int m0 = blockIdx.y * 128;
    if (m0 >= M) return;
    int n0 = blockIdx.x * 128;

    extern __shared__ char smem[];
    uint32_t sb = smem_u32(smem);

    int t = threadIdx.x, lane = t & 31, wid = t >> 5;

    // ---- loader mapping: thread t -> row t>>1, cols (t&1)*16 + {0,8} ----
    int lr = t >> 1;
    int lc = (t & 1) * 16;
    bool av = (m0 + lr) < M;
    uint32_t aSz = av ? 16u : 0u;
    int arow;
    if (EPI <= 1) arow = ROUTED ? (av ? d_tok[base + m0 + lr] : 0)
                                : (av ? m0 + lr : 0);
    else          arow = base + (av ? m0 + lr : 0);
    const __half* aP = A + (size_t)arow * K + lc;
    const __half* bP = W + offB + eoff + (size_t)(n0 + lr) * K + lc;
    uint32_t stOff = (uint32_t)(lr * LDS + lc) * 2u;

    int wm = (wid & 3) * 32;
    int wn = (wid >> 2) * 64;

    float acc[2][8][4];
    #pragma unroll
    for (int i = 0; i < 2; ++i)
        #pragma unroll
        for (int j = 0; j < 8; ++j)
            #pragma unroll
            for (int q = 0; q < 4; ++q) acc[i][j][q] = 0.f;

    int KT = K / BK;
    // prologue: stages 0..2
    #pragma unroll
    for (int p = 0; p < NSTG - 1; ++p) {
        uint32_t s0 = sb + p * 2 * TILE;
        int k0 = p * BK;
        cpa16(s0 + stOff,             aP + k0,     aSz);
        cpa16(s0 + stOff + 16,        aP + k0 + 8, aSz);
        cpa16(s0 + TILE + stOff,      bP + k0,     16);
        cpa16(s0 + TILE + stOff + 16, bP + k0 + 8, 16);
        cpa_commit();
    }

    for (int ch = 0; ch < KT; ++ch) {
        cpa_wait2();
        __syncthreads();
        if (ch + NSTG - 1 < KT) {
            int stg = (ch + NSTG - 1) % NSTG;
            uint32_t s0 = sb + stg * 2 * TILE;
            int k0 = (ch + NSTG - 1) * BK;
            cpa16(s0 + stOff,             aP + k0,     aSz);
            cpa16(s0 + stOff + 16,        aP + k0 + 8, aSz);
            cpa16(s0 + TILE + stOff,      bP + k0,     16);
            cpa16(s0 + TILE + stOff + 16, bP + k0 + 8, 16);
        }
        cpa_commit();

        uint32_t cs = sb + (ch % NSTG) * 2 * TILE;
        uint32_t sA = cs, sB = cs + TILE;
        #pragma unroll
        for (int s = 0; s < 2; ++s) {
            uint32_t b[8][2];
            #pragma unroll
            for (int jj = 0; jj < 4; ++jj) {
                uint32_t addr = sB + (uint32_t)(((wn + jj * 16 + (lane & 7)
                              + ((lane >> 4) & 1) * 8) * LDS
                              + s * 16 + ((lane >> 3) & 1) * 8) * 2);
                ldsm_x4(b[2 * jj][0], b[2 * jj][1],
                        b[2 * jj + 1][0], b[2 * jj + 1][1], addr);
            }
            #pragma unroll
            for (int i = 0; i < 2; ++i) {
                uint32_t aOff = (uint32_t)(((wm + i * 16 + (lane & 15)) * LDS
                              + s * 16 + (lane >> 4) * 8) * 2);
                uint32_t ar[4];
                ldsm_x4(ar[0], ar[1], ar[2], ar[3], sA + aOff);
                #pragma unroll
                for (int j = 0; j < 8; ++j)
                    mma_f16(acc[i][j], ar, b[j]);
            }
        }
    }

    // ---- epilogue ----
    #pragma unroll
    for (int i = 0; i < 2; ++i) {
        #pragma unroll
        for (int hh = 0; hh < 2; ++hh) {
            int r  = wm + i * 16 + (lane >> 2) + hh * 8;
            int mg = m0 + r;
            if (mg >= M) continue;
            if (EPI == 0) {
                size_t orow = (size_t)(ROUTED ? base + mg : mg);
                float* op = Fout + orow * (size_t)N + n0;
                #pragma unroll
                for (int j = 0; j < 8; ++j) {
                    int c = wn + j * 8 + (lane & 3) * 2;
                    *(float2*)(op + c) = make_float2(acc[i][j][hh * 2],
                                                     acc[i][j][hh * 2 + 1]);
                }
            } else if (EPI == 1) {
                size_t orow = (size_t)(ROUTED ? base + mg : mg);
                const float* gp = gIn + orow * (size_t)N + n0;
                __half* ph = actH + orow * (size_t)N + n0;
                #pragma unroll
                for (int j = 0; j < 8; ++j) {
                    int c = wn + j * 8 + (lane & 3) * 2;
                    float2 g2 = *(const float2*)(gp + c);
                    float u0 = acc[i][j][hh * 2], u1 = acc[i][j][hh * 2 + 1];
                    float a0 = g2.x / (1.f + expf(-g2.x)) * u0;
                    float a1 = g2.y / (1.f + expf(-g2.y)) * u1;
                    *(__half2*)(ph + c) = __floats2half2_rn(a0, a1);
                }
            } else if (EPI == 2) {
                float* op = Fout + (size_t)mg * HDIM + n0;
                #pragma unroll
                for (int j = 0; j < 8; ++j) {
                    int c = wn + j * 8 + (lane & 3) * 2;
                    *(float2*)(op + c) = make_float2(acc[i][j][hh * 2],
                                                     acc[i][j][hh * 2 + 1]);
                }
            } else {
                int   slot = base + mg;
                int   tok  = d_tok[slot];
                float w    = d_wt[slot];
                float* op  = Fout + (size_t)tok * HDIM + n0;
                #pragma unroll
                for (int j = 0; j < 8; ++j) {
                    int c = wn + j * 8 + (lane & 3) * 2;
                    atomicAdd(op + c,     w * acc[i][j][hh * 2]);
                    atomicAdd(op + c + 1, w * acc[i][j][hh * 2 + 1]);
                }
            }
        }
    }
}

// ---------------- launch ----------------
extern "C" void kernel_launch(void* const* d_in, const int* in_sizes, int n_in,
                              void* d_out, int out_size) {
    const float* x  = (const float*)d_in[0];
    const float* gw = (const float*)d_in[1];
    const float* eg = (const float*)d_in[2];
    const float* eu = (const float*)d_in[3];
    const float* ed = (const float*)d_in[4];
    const float* sg = (const float*)d_in[5];
    const float* su = (const float*)d_in[6];
    const float* sd = (const float*)d_in[7];
    float* out = (float*)d_out;

    __half *wH, *xH, *actH;
    float* gbuf;
    cudaGetSymbolAddress((void**)&wH,   d_wH);
    cudaGetSymbolAddress((void**)&xH,   d_xH);
    cudaGetSymbolAddress((void**)&actH, d_actH);
    cudaGetSymbolAddress((void**)&gbuf, d_gbuf);

    cudaFuncSetAttribute(gemm<0,false>, cudaFuncAttributeMaxDynamicSharedMemorySize, SMEM_GEMM);
    cudaFuncSetAttribute(gemm<1,false>, cudaFuncAttributeMaxDynamicSharedMemorySize, SMEM_GEMM);
    cudaFuncSetAttribute(gemm<2,false>, cudaFuncAttributeMaxDynamicSharedMemorySize, SMEM_GEMM);
    cudaFuncSetAttribute(gemm<0,true>,  cudaFuncAttributeMaxDynamicSharedMemorySize, SMEM_GEMM);
    cudaFuncSetAttribute(gemm<1,true>,  cudaFuncAttributeMaxDynamicSharedMemorySize, SMEM_GEMM);
    cudaFuncSetAttribute(gemm<3,true>,  cudaFuncAttributeMaxDynamicSharedMemorySize, SMEM_GEMM);

    // routing
    zero_kernel<<<1, 32>>>();
    router_kernel<<<N_TOK, 256>>>(x, gw);
    offsets_kernel<<<1, 32>>>();
    scatter_kernel<<<4, 256>>>();

    // conversions (fp32 -> fp16)
    auto cvt = [&](const float* src, __half* dst, size_t n) {
        int n8 = (int)(n / 8);
        cvt_h_kernel<<<(n8 + 255) / 256, 256>>>(src, dst, n8);
    };
    cvt(eg, wH + OFF_EG, (size_t)NEXP * IDIM * HDIM);
    cvt(eu, wH + OFF_EU, (size_t)NEXP * IDIM * HDIM);
    cvt(ed, wH + OFF_ED, (size_t)NEXP * HDIM * IDIM);
    cvt(sg, wH + OFF_SG, (size_t)ISH * HDIM);
    cvt(su, wH + OFF_SU, (size_t)ISH * HDIM);
    cvt(sd, wH + OFF_SD, (size_t)HDIM * ISH);
    cvt(x,  xH,          (size_t)N_TOK * HDIM);

    // shared expert: gate -> gbuf, up+silu -> act, down -> out (initializes out)
    gemm<0,false><<<dim3(ISH / 128, N_TOK / 128, 1), 256, SMEM_GEMM>>>(
        wH, OFF_SG, xH, gbuf, nullptr, nullptr, N_TOK, ISH, HDIM);
    gemm<1,false><<<dim3(ISH / 128, N_TOK / 128, 1), 256, SMEM_GEMM>>>(
        wH, OFF_SU, xH, nullptr, actH, gbuf, N_TOK, ISH, HDIM);
    gemm<2,false><<<dim3(HDIM / 128, N_TOK / 128, 1), 256, SMEM_GEMM>>>(
        wH, OFF_SD, actH, out, nullptr, nullptr, N_TOK, HDIM, ISH);

    // routed experts
    gemm<0,true><<<dim3(IDIM / 128, N_TOK / 128, NEXP), 256, SMEM_GEMM>>>(
        wH, OFF_EG, xH, gbuf, nullptr, nullptr, 0, IDIM, HDIM);
    gemm<1,true><<<dim3(IDIM / 128, N_TOK / 128, NEXP), 256, SMEM_GEMM>>>(
        wH, OFF_EU, xH, nullptr, actH, gbuf, 0, IDIM, HDIM);
    gemm<3,true><<<dim3(HDIM / 128, N_TOK / 128, NEXP), 256, SMEM_GEMM>>>(
        wH, OFF_ED, actH, out, nullptr, nullptr, 0, HDIM, IDIM);
}